// round 13
// baseline (speedup 1.0000x reference)
#include <cuda_runtime.h>
#include <cuda_bf16.h>
#include <cstdint>

#define NB 32
#define NL 128
#define ND 512
#define NROWS (NB*NL)   // 4096

// ================= scratch (device code references ONLY — GB300 ATS trap) =================
__device__ float g_wq_new[NROWS*ND];
__device__ float g_wq_cur[NROWS*ND];
__device__ float g_uh_new[NROWS*ND];
__device__ float g_uh_cur[NROWS*ND];
__device__ float g_c1[NROWS*ND];
__device__ float g_c2[NROWS*ND];

__device__ __nv_bfloat16 g_no_hi [NROWS*ND];
__device__ __nv_bfloat16 g_no_lo [NROWS*ND];
__device__ __nv_bfloat16 g_cur_hi[NROWS*ND];
__device__ __nv_bfloat16 g_cur_lo[NROWS*ND];
__device__ __nv_bfloat16 g_Wqt_hi[ND*ND];      // Wq^T  [N=512][K=512]
__device__ __nv_bfloat16 g_Wqt_lo[ND*ND];
__device__ __nv_bfloat16 g_Wct_hi[ND*ND];
__device__ __nv_bfloat16 g_Wct_lo[ND*ND];
__device__ __nv_bfloat16 g_Wot_hi[ND*2*ND];    // Wout^T [N=512][K=1024]
__device__ __nv_bfloat16 g_Wot_lo[ND*2*ND];
__device__ __nv_bfloat16 g_amix_hi[NROWS*2*ND];// mixed A for out gemm [4096][1024]
__device__ __nv_bfloat16 g_amix_lo[NROWS*2*ND];

// ================= helpers =================
__device__ __forceinline__ uint32_t smem_u32(const void* p){
    uint32_t a;
    asm("{ .reg .u64 t; cvta.to.shared.u64 t, %1; cvt.u32.u64 %0, t; }" : "=r"(a) : "l"(p));
    return a;
}
__device__ __forceinline__ float tanh_apx(float x){
    float y; asm("tanh.approx.f32 %0, %1;" : "=f"(y) : "f"(x)); return y;
}
__device__ __forceinline__ void split2(float x, __nv_bfloat16& h, __nv_bfloat16& l){
    h = __float2bfloat16_rn(x);
    l = __float2bfloat16_rn(x - __bfloat162float(h));
}
__device__ __forceinline__ uint32_t lds32(uint32_t a){
    uint32_t v; asm volatile("ld.shared.b32 %0, [%1];" : "=r"(v) : "r"(a)); return v;
}
__device__ __forceinline__ void mma16816(float* c, const uint32_t* a, const uint32_t* b){
    asm volatile("mma.sync.aligned.m16n8k16.row.col.f32.bf16.bf16.f32 "
        "{%0,%1,%2,%3},{%4,%5,%6,%7},{%8,%9},{%0,%1,%2,%3};"
        : "+f"(c[0]),"+f"(c[1]),"+f"(c[2]),"+f"(c[3])
        : "r"(a[0]),"r"(a[1]),"r"(a[2]),"r"(a[3]),"r"(b[0]),"r"(b[1]));
}

// ================= convert kernels (selector-based) =================
__global__ void __launch_bounds__(256) split_kernel(const float* __restrict__ in, int which)
{
    __nv_bfloat16* hi = which ? g_cur_hi : g_no_hi;
    __nv_bfloat16* lo = which ? g_cur_lo : g_no_lo;
    int i = blockIdx.x*256 + threadIdx.x;
    float4 v = ((const float4*)in)[i];
    __nv_bfloat16 h0,l0,h1,l1,h2,l2,h3,l3;
    split2(v.x,h0,l0); split2(v.y,h1,l1); split2(v.z,h2,l2); split2(v.w,h3,l3);
    __nv_bfloat162* H = (__nv_bfloat162*)hi; __nv_bfloat162* L = (__nv_bfloat162*)lo;
    H[2*i]   = __nv_bfloat162(h0,h1); H[2*i+1] = __nv_bfloat162(h2,h3);
    L[2*i]   = __nv_bfloat162(l0,l1); L[2*i+1] = __nv_bfloat162(l2,l3);
}

// in[R][C] fp32 -> out[C][R] hi/lo bf16 (transpose+split). grid (C/32, R/32), block (32,8)
__global__ void __launch_bounds__(256) splitT_kernel(
    const float* __restrict__ in, int which, int R, int C)
{
    __nv_bfloat16 *hi, *lo;
    if      (which == 0){ hi = g_Wqt_hi; lo = g_Wqt_lo; }
    else if (which == 1){ hi = g_Wct_hi; lo = g_Wct_lo; }
    else                { hi = g_Wot_hi; lo = g_Wot_lo; }
    __shared__ float t[32][33];
    int bx = blockIdx.x*32, by = blockIdx.y*32;
    int x = threadIdx.x, y = threadIdx.y;
    #pragma unroll
    for (int i=0;i<32;i+=8)
        t[y+i][x] = in[(size_t)(by+y+i)*C + bx + x];
    __syncthreads();
    #pragma unroll
    for (int i=0;i<32;i+=8){
        float v = t[x][y+i];
        __nv_bfloat16 h,l; split2(v,h,l);
        size_t o = (size_t)(bx+y+i)*R + by + x;
        hi[o]=h; lo[o]=l;
    }
}

__global__ void __launch_bounds__(256) mix_split_kernel(
    const float* __restrict__ no, const float* __restrict__ cur, const float* __restrict__ mixp)
{
    float m = __ldg(mixp);
    int i = blockIdx.x*256 + threadIdx.x;
    int r = i >> 8;
    int col = (i & 255)*4;
    const float *p1,*p2; int sc;
    if (col < ND){ p1=g_c1; p2=g_c2; sc=col; } else { p1=no; p2=cur; sc=col-ND; }
    float4 a = *(const float4*)(p1 + (size_t)r*ND + sc);
    float4 b = *(const float4*)(p2 + (size_t)r*ND + sc);
    float4 w;
    w.x=a.x+m*(b.x-a.x); w.y=a.y+m*(b.y-a.y); w.z=a.z+m*(b.z-a.z); w.w=a.w+m*(b.w-a.w);
    __nv_bfloat16 h0,l0,h1,l1,h2,l2,h3,l3;
    split2(w.x,h0,l0); split2(w.y,h1,l1); split2(w.z,h2,l2); split2(w.w,h3,l3);
    size_t o = (size_t)r*2*ND + col;
    *(__nv_bfloat162*)(g_amix_hi+o)   = __nv_bfloat162(h0,h1);
    *(__nv_bfloat162*)(g_amix_hi+o+2) = __nv_bfloat162(h2,h3);
    *(__nv_bfloat162*)(g_amix_lo+o)   = __nv_bfloat162(l0,l1);
    *(__nv_bfloat162*)(g_amix_lo+o+2) = __nv_bfloat162(l2,l3);
}

// ================= mma.sync split-bf16 GEMM: 4 warps, 64x64/warp, reg-prefetch =================
// CTA 128x128, 128 threads. Register prefetch of chunk c+1 overlaps global latency
// with the ~800-cyc mma phase of chunk c (R8 pattern + R11 tile).
#define BK    32
#define LDSW  40                 // padded row length (bf16 elems): 80B stride, conflict-free
#define MATE  (128*LDSW)         // elems per matrix tile (5120)
#define GSMEM (4*MATE*2)         // 40960 B

__device__ __forceinline__ void gemm_body(
    const __nv_bfloat16* __restrict__ Ahi, const __nv_bfloat16* __restrict__ Alo,
    const __nv_bfloat16* __restrict__ Bhi, const __nv_bfloat16* __restrict__ Blo,
    int K, const float* __restrict__ bias, float* __restrict__ C, int ldc)
{
    extern __shared__ __nv_bfloat16 sm[];
    uint32_t sb = smem_u32(sm);
    int tid = threadIdx.x, lane = tid & 31, wid = tid >> 5;
    int wm = wid & 1, wn = wid >> 1;          // wn in {0,1}
    int m0 = blockIdx.x*128, n0 = blockIdx.y*128;
    int g = lane >> 2, tig = lane & 3;

    const __nv_bfloat16* gp[4] = {Ahi, Alo, Bhi, Blo};
    const int rb[4] = {m0, m0, n0, n0};

    float acc[4][8][4];
    #pragma unroll
    for (int i=0;i<4;i++)
        #pragma unroll
        for (int j=0;j<8;j++)
            #pragma unroll
            for (int k=0;k<4;k++) acc[i][j][k]=0.f;

    const int chunks = K / BK;
    uint4 stg[16];

    // prefetch chunk 0: 16 uint4/thread (4 matrices x 512 uint4, 128 threads)
    #pragma unroll
    for (int i=0;i<16;i++){
        const int mat = i >> 2;
        int idx = tid + (i & 3)*128, row = idx >> 2, kc = idx & 3;
        stg[i] = *(const uint4*)(gp[mat] + (size_t)(rb[mat]+row)*K + kc*8);
    }

    for (int c = 0; c < chunks; c++){
        __syncthreads();   // previous chunk's compute done reading smem
        #pragma unroll
        for (int i=0;i<16;i++){
            const int mat = i >> 2;
            int idx = tid + (i & 3)*128, row = idx >> 2, kc = idx & 3;
            *(uint4*)(sm + mat*MATE + row*LDSW + kc*8) = stg[i];
        }
        __syncthreads();
        if (c+1 < chunks){
            int k0 = (c+1)*BK;
            #pragma unroll
            for (int i=0;i<16;i++){
                const int mat = i >> 2;
                int idx = tid + (i & 3)*128, row = idx >> 2, kc = idx & 3;
                stg[i] = *(const uint4*)(gp[mat] + (size_t)(rb[mat]+row)*K + k0 + kc*8);
            }
        }

        #pragma unroll
        for (int ks=0; ks<2; ks++){
            uint32_t ah[4][4], al[4][4];
            // A frags: a0=(g,2t) a1=(g+8,2t) a2=(g,2t+8) a3=(g+8,2t+8)
            #pragma unroll
            for (int mt=0;mt<4;mt++){
                uint32_t o00 = (uint32_t)((wm*64 + mt*16 + g)*LDSW + ks*16 + tig*2)*2;
                uint32_t o10 = o00 + 8*LDSW*2;
                uint32_t aH = sb + 0*MATE*2, aL = sb + 1*MATE*2;
                ah[mt][0] = lds32(aH + o00);
                ah[mt][1] = lds32(aH + o10);
                ah[mt][2] = lds32(aH + o00 + 16);
                ah[mt][3] = lds32(aH + o10 + 16);
                al[mt][0] = lds32(aL + o00);
                al[mt][1] = lds32(aL + o10);
                al[mt][2] = lds32(aL + o00 + 16);
                al[mt][3] = lds32(aL + o10 + 16);
            }
            // B frags (B^T stored [n][k]): b0=(k=2t,n=g) b1=(k=2t+8,n=g)
            #pragma unroll
            for (int nt=0;nt<8;nt++){
                uint32_t o0 = (uint32_t)((wn*64 + nt*8 + g)*LDSW + ks*16 + tig*2)*2;
                uint32_t bH = sb + 2*MATE*2, bL = sb + 3*MATE*2;
                uint32_t bh[2], bl[2];
                bh[0] = lds32(bH + o0);
                bh[1] = lds32(bH + o0 + 16);
                bl[0] = lds32(bL + o0);
                bl[1] = lds32(bL + o0 + 16);
                #pragma unroll
                for (int mt=0;mt<4;mt++){
                    mma16816(acc[mt][nt], ah[mt], bh);
                    mma16816(acc[mt][nt], ah[mt], bl);
                    mma16816(acc[mt][nt], al[mt], bh);
                }
            }
        }
    }

    // epilogue: c0,c1 -> (g, 2t..2t+1); c2,c3 -> (g+8, 2t..2t+1)
    int t2 = tig*2;
    #pragma unroll
    for (int mt=0;mt<4;mt++){
        int m = m0 + wm*64 + mt*16 + g;
        #pragma unroll
        for (int nt=0;nt<8;nt++){
            int n = n0 + wn*64 + nt*8 + t2;
            float b0v = bias ? bias[n]   : 0.f;
            float b1v = bias ? bias[n+1] : 0.f;
            float2 r0; r0.x = acc[mt][nt][0] + b0v; r0.y = acc[mt][nt][1] + b1v;
            float2 r1; r1.x = acc[mt][nt][2] + b0v; r1.y = acc[mt][nt][3] + b1v;
            *(float2*)(C + (size_t)m*ldc + n)     = r0;
            *(float2*)(C + (size_t)(m+8)*ldc + n) = r1;
        }
    }
}

__global__ void __launch_bounds__(128,2) gemm_proj_kernel(const float* __restrict__ bq){
    int combo = blockIdx.z;
    const __nv_bfloat16 *Ah,*Al,*Bh,*Bl; const float* bias; float* C;
    switch (combo){
    case 0: Ah=g_no_hi;  Al=g_no_lo;  Bh=g_Wqt_hi; Bl=g_Wqt_lo; bias=bq;      C=g_wq_new; break;
    case 1: Ah=g_cur_hi; Al=g_cur_lo; Bh=g_Wqt_hi; Bl=g_Wqt_lo; bias=bq;      C=g_wq_cur; break;
    case 2: Ah=g_no_hi;  Al=g_no_lo;  Bh=g_Wct_hi; Bl=g_Wct_lo; bias=nullptr; C=g_uh_new; break;
    default:Ah=g_cur_hi; Al=g_cur_lo; Bh=g_Wct_hi; Bl=g_Wct_lo; bias=nullptr; C=g_uh_cur; break;
    }
    gemm_body(Ah, Al, Bh, Bl, ND, bias, C, ND);
}

__global__ void __launch_bounds__(128,2) gemm_out_kernel(const float* __restrict__ bout, float* __restrict__ out){
    gemm_body(g_amix_hi, g_amix_lo, g_Wot_hi, g_Wot_lo, 2*ND, bout, out, ND);
}

// ================= fused attention: 2 t-rows per warp (R10-proven) =================
__global__ void __launch_bounds__(256) attn_kernel(
    const float* __restrict__ cur, const float* __restrict__ no,
    const float* __restrict__ v)
{
    __shared__ float sc[16][128];
    __shared__ float pm[128][16];

    int dir = blockIdx.z;
    int bb  = blockIdx.y;
    int t0  = blockIdx.x * 16;
    const float* wq  = dir ? g_wq_cur : g_wq_new;
    const float* uh  = dir ? g_uh_new : g_uh_cur;
    const float* mem = dir ? no       : cur;
    float*       cO  = dir ? g_c2     : g_c1;

    int tid = threadIdx.x, w = tid >> 5, lane = tid & 31;

    float4 v4[4], qa[4], qb[4];
    {
        const float* ra = wq + (size_t)(bb*NL + t0 + w)*ND;
        const float* rb = wq + (size_t)(bb*NL + t0 + w + 8)*ND;
        #pragma unroll
        for (int i=0;i<4;i++){
            v4[i] = *(const float4*)(v  + lane*4 + 128*i);
            qa[i] = *(const float4*)(ra + lane*4 + 128*i);
            qb[i] = *(const float4*)(rb + lane*4 + 128*i);
        }
    }
    for (int s=0; s<NL; s++){
        const float* urow = uh + (size_t)(bb*NL + s)*ND;
        float acca = 0.f, accb = 0.f;
        #pragma unroll
        for (int i=0;i<4;i++){
            float4 u = *(const float4*)(urow + lane*4 + 128*i);
            acca += v4[i].x * tanh_apx(qa[i].x + u.x);
            accb += v4[i].x * tanh_apx(qb[i].x + u.x);
            acca += v4[i].y * tanh_apx(qa[i].y + u.y);
            accb += v4[i].y * tanh_apx(qb[i].y + u.y);
            acca += v4[i].z * tanh_apx(qa[i].z + u.z);
            accb += v4[i].z * tanh_apx(qb[i].z + u.z);
            acca += v4[i].w * tanh_apx(qa[i].w + u.w);
            accb += v4[i].w * tanh_apx(qb[i].w + u.w);
        }
        #pragma unroll
        for (int off=16; off; off>>=1){
            acca += __shfl_xor_sync(0xffffffffu, acca, off);
            accb += __shfl_xor_sync(0xffffffffu, accb, off);
        }
        if (lane == 0){ sc[w][s] = acca; sc[w+8][s] = accb; }
    }
    __syncwarp();

    #pragma unroll
    for (int rr=0; rr<2; rr++){
        int r = w + rr*8;
        float sv[4];
        #pragma unroll
        for (int i=0;i<4;i++) sv[i] = sc[r][lane + 32*i];
        float mx = fmaxf(fmaxf(sv[0],sv[1]), fmaxf(sv[2],sv[3]));
        #pragma unroll
        for (int off=16; off; off>>=1)
            mx = fmaxf(mx, __shfl_xor_sync(0xffffffffu, mx, off));
        float e[4], sum = 0.f;
        #pragma unroll
        for (int i=0;i<4;i++){ e[i] = __expf(sv[i]-mx); sum += e[i]; }
        #pragma unroll
        for (int off=16; off; off>>=1)
            sum += __shfl_xor_sync(0xffffffffu, sum, off);
        float inv = 1.f / sum;
        #pragma unroll
        for (int i=0;i<4;i++) pm[lane + 32*i][r] = e[i]*inv;
    }
    __syncthreads();

    int d0 = tid, d1 = tid + 256;
    float a0[16], a1[16];
    #pragma unroll
    for (int t=0;t<16;t++){ a0[t]=0.f; a1[t]=0.f; }
    for (int s=0; s<NL; s++){
        const float* mrow = mem + (size_t)(bb*NL + s)*ND;
        float m0v = __ldg(mrow + d0);
        float m1v = __ldg(mrow + d1);
        #pragma unroll
        for (int q4i=0;q4i<4;q4i++){
            float4 p = *(const float4*)&pm[s][q4i*4];
            a0[q4i*4+0]+=p.x*m0v; a1[q4i*4+0]+=p.x*m1v;
            a0[q4i*4+1]+=p.y*m0v; a1[q4i*4+1]+=p.y*m1v;
            a0[q4i*4+2]+=p.z*m0v; a1[q4i*4+2]+=p.z*m1v;
            a0[q4i*4+3]+=p.w*m0v; a1[q4i*4+3]+=p.w*m1v;
        }
    }
    #pragma unroll
    for (int t=0;t<16;t++){
        float* crow = cO + (size_t)(bb*NL + t0 + t)*ND;
        crow[d0] = a0[t];
        crow[d1] = a1[t];
    }
}

// ================= launch =================
extern "C" void kernel_launch(void* const* d_in, const int* in_sizes, int n_in,
                              void* d_out, int out_size)
{
    const float* cur  = (const float*)d_in[0];
    const float* no   = (const float*)d_in[1];
    const float* Wq   = (const float*)d_in[2];
    const float* bq   = (const float*)d_in[3];
    const float* Wc   = (const float*)d_in[4];
    const float* v    = (const float*)d_in[5];
    const float* Wout = (const float*)d_in[6];
    const float* bout = (const float*)d_in[7];
    const float* mix  = (const float*)d_in[8];
    float* out = (float*)d_out;

    split_kernel<<<2048, 256>>>(no,  0);
    split_kernel<<<2048, 256>>>(cur, 1);
    splitT_kernel<<<dim3(ND/32, ND/32),   dim3(32,8)>>>(Wq,   0, ND,   ND);
    splitT_kernel<<<dim3(ND/32, ND/32),   dim3(32,8)>>>(Wc,   1, ND,   ND);
    splitT_kernel<<<dim3(ND/32, 2*ND/32), dim3(32,8)>>>(Wout, 2, 2*ND, ND);

    gemm_proj_kernel<<<dim3(NROWS/128, ND/128, 4), 128, GSMEM>>>(bq);

    attn_kernel<<<dim3(NL/16, NB, 2), 256>>>(cur, no, v);

    mix_split_kernel<<<NROWS*2*ND/(4*256), 256>>>(no, cur, mix);
    gemm_out_kernel<<<dim3(NROWS/128, ND/128), 128, GSMEM>>>(bout, out);
}

// round 14
// speedup vs baseline: 1.1188x; 1.1188x over previous
#include <cuda_runtime.h>
#include <cuda_fp16.h>
#include <cstdint>

#define NB 32
#define NL 128
#define ND 512
#define NROWS (NB*NL)   // 4096

// ================= scratch (device code references ONLY — GB300 ATS trap) =================
__device__ float g_wq_new[NROWS*ND];
__device__ float g_wq_cur[NROWS*ND];
__device__ float g_uh_new[NROWS*ND];
__device__ float g_uh_cur[NROWS*ND];
__device__ float g_c1[NROWS*ND];
__device__ float g_c2[NROWS*ND];

// fp16 operands: activations split 2-way (hi+lo ~ 22 mantissa bits), weights single fp16
__device__ __half g_no_hi [NROWS*ND];
__device__ __half g_no_lo [NROWS*ND];
__device__ __half g_cur_hi[NROWS*ND];
__device__ __half g_cur_lo[NROWS*ND];
__device__ __half g_Wqt[ND*ND];        // Wq^T  [N=512][K=512]
__device__ __half g_Wct[ND*ND];
__device__ __half g_Wot[ND*2*ND];      // Wout^T [N=512][K=1024]
__device__ __half g_amix_hi[NROWS*2*ND];
__device__ __half g_amix_lo[NROWS*2*ND];

// ================= helpers =================
__device__ __forceinline__ uint32_t smem_u32(const void* p){
    uint32_t a;
    asm("{ .reg .u64 t; cvta.to.shared.u64 t, %1; cvt.u32.u64 %0, t; }" : "=r"(a) : "l"(p));
    return a;
}
__device__ __forceinline__ float tanh_apx(float x){
    float y; asm("tanh.approx.f32 %0, %1;" : "=f"(y) : "f"(x)); return y;
}
__device__ __forceinline__ void split2h(float x, __half& h, __half& l){
    h = __float2half_rn(x);
    l = __float2half_rn(x - __half2float(h));
}
__device__ __forceinline__ uint32_t lds32(uint32_t a){
    uint32_t v; asm volatile("ld.shared.b32 %0, [%1];" : "=r"(v) : "r"(a)); return v;
}
__device__ __forceinline__ void mma16816h(float* c, const uint32_t* a, const uint32_t* b){
    asm volatile("mma.sync.aligned.m16n8k16.row.col.f32.f16.f16.f32 "
        "{%0,%1,%2,%3},{%4,%5,%6,%7},{%8,%9},{%0,%1,%2,%3};"
        : "+f"(c[0]),"+f"(c[1]),"+f"(c[2]),"+f"(c[3])
        : "r"(a[0]),"r"(a[1]),"r"(a[2]),"r"(a[3]),"r"(b[0]),"r"(b[1]));
}
__device__ __forceinline__ void cpa16(uint32_t s, const void* g){
    asm volatile("cp.async.cg.shared.global [%0], [%1], 16;" :: "r"(s),"l"(g) : "memory");
}

// ================= convert kernels (selector-based) =================
__global__ void __launch_bounds__(256) split_kernel(const float* __restrict__ in, int which)
{
    __half* hi = which ? g_cur_hi : g_no_hi;
    __half* lo = which ? g_cur_lo : g_no_lo;
    int i = blockIdx.x*256 + threadIdx.x;
    float4 v = ((const float4*)in)[i];
    __half h0,l0,h1,l1,h2,l2,h3,l3;
    split2h(v.x,h0,l0); split2h(v.y,h1,l1); split2h(v.z,h2,l2); split2h(v.w,h3,l3);
    __half2* H = (__half2*)hi; __half2* L = (__half2*)lo;
    H[2*i]   = __half2(h0,h1); H[2*i+1] = __half2(h2,h3);
    L[2*i]   = __half2(l0,l1); L[2*i+1] = __half2(l2,l3);
}

// in[R][C] fp32 -> out[C][R] fp16 (transpose+round). grid (C/32, R/32), block (32,8)
__global__ void __launch_bounds__(256) splitT_kernel(
    const float* __restrict__ in, int which, int R, int C)
{
    __half* dst = (which==0) ? g_Wqt : (which==1) ? g_Wct : g_Wot;
    __shared__ float t[32][33];
    int bx = blockIdx.x*32, by = blockIdx.y*32;
    int x = threadIdx.x, y = threadIdx.y;
    #pragma unroll
    for (int i=0;i<32;i+=8)
        t[y+i][x] = in[(size_t)(by+y+i)*C + bx + x];
    __syncthreads();
    #pragma unroll
    for (int i=0;i<32;i+=8)
        dst[(size_t)(bx+y+i)*R + by + x] = __float2half_rn(t[x][y+i]);
}

__global__ void __launch_bounds__(256) mix_split_kernel(
    const float* __restrict__ no, const float* __restrict__ cur, const float* __restrict__ mixp)
{
    float m = __ldg(mixp);
    int i = blockIdx.x*256 + threadIdx.x;
    int r = i >> 8;
    int col = (i & 255)*4;
    const float *p1,*p2; int sc;
    if (col < ND){ p1=g_c1; p2=g_c2; sc=col; } else { p1=no; p2=cur; sc=col-ND; }
    float4 a = *(const float4*)(p1 + (size_t)r*ND + sc);
    float4 b = *(const float4*)(p2 + (size_t)r*ND + sc);
    float4 w;
    w.x=a.x+m*(b.x-a.x); w.y=a.y+m*(b.y-a.y); w.z=a.z+m*(b.z-a.z); w.w=a.w+m*(b.w-a.w);
    __half h0,l0,h1,l1,h2,l2,h3,l3;
    split2h(w.x,h0,l0); split2h(w.y,h1,l1); split2h(w.z,h2,l2); split2h(w.w,h3,l3);
    size_t o = (size_t)r*2*ND + col;
    *(__half2*)(g_amix_hi+o)   = __half2(h0,h1);
    *(__half2*)(g_amix_hi+o+2) = __half2(h2,h3);
    *(__half2*)(g_amix_lo+o)   = __half2(l0,l1);
    *(__half2*)(g_amix_lo+o+2) = __half2(l2,l3);
}

// ================= 2-pass split-fp16 GEMM, cp.async double-buffered =================
// C = (Ahi+Alo) @ B^T, fp32 accum. CTA 128x128, 4 warps (64x64 each), BK=16.
// 3 staged matrices (Ahi, Alo, B), 2 stages, 48B row stride (16B-aligned, conflict-free).
#define BK     16
#define LDSW   24                  // fp16 elems per row slot: 48 B stride
#define MATE   (128*LDSW)          // 3072 elems per matrix tile
#define STAGEB (3*MATE*2)          // 18432 B per stage
#define GSMEM  (2*STAGEB)          // 36864 B  (< 48 KB: no attribute needed)

__device__ __forceinline__ void gemm_body(
    const __half* __restrict__ Ahi, const __half* __restrict__ Alo,
    const __half* __restrict__ B, int K,
    const float* __restrict__ bias, float* __restrict__ C, int ldc)
{
    extern __shared__ __half sm[];
    uint32_t sb = smem_u32(sm);
    int tid = threadIdx.x, lane = tid & 31, wid = tid >> 5;
    int wm = wid & 1, wn = wid >> 1;          // wn in {0,1}
    int m0 = blockIdx.x*128, n0 = blockIdx.y*128;
    int g = lane >> 2, tig = lane & 3;

    const __half* gp[3] = {Ahi, Alo, B};
    const int rb[3] = {m0, m0, n0};

    float acc[4][8][4];
    #pragma unroll
    for (int i=0;i<4;i++)
        #pragma unroll
        for (int j=0;j<8;j++)
            #pragma unroll
            for (int k=0;k<4;k++) acc[i][j][k]=0.f;

    const int chunks = K / BK;

    // issue one stage: 3 matrices x 128 rows x 32B (= 2x16B per row), 6 cp.async/thread
    #define ISSUE(stq, k0q) do{                                                 \
        uint32_t sbase = sb + (uint32_t)(stq)*STAGEB;                           \
        _Pragma("unroll")                                                       \
        for (int mat=0; mat<3; mat++){                                          \
            _Pragma("unroll")                                                   \
            for (int j=0;j<2;j++){                                              \
                int id = tid + j*128;                                           \
                int row = id >> 1, hf = id & 1;                                 \
                uint32_t sa = sbase + (uint32_t)mat*(MATE*2) + row*48 + hf*16;  \
                cpa16(sa, gp[mat] + (size_t)(rb[mat]+row)*K + (k0q) + hf*8);    \
            }                                                                   \
        }                                                                       \
        asm volatile("cp.async.commit_group;" ::: "memory");                    \
    }while(0)

    ISSUE(0, 0);
    ISSUE(1, BK);

    for (int c = 0; c < chunks; c++){
        if (c+1 < chunks) asm volatile("cp.async.wait_group 1;" ::: "memory");
        else              asm volatile("cp.async.wait_group 0;" ::: "memory");
        __syncthreads();

        uint32_t sA  = sb + (uint32_t)(c & 1)*STAGEB;
        uint32_t sAl = sA + MATE*2;
        uint32_t sB  = sA + 2*(MATE*2);

        // A frags (k16): a0=(g,2t) a1=(g+8,2t) a2=(g,2t+8) a3=(g+8,2t+8)
        uint32_t ah[4][4], al[4][4];
        #pragma unroll
        for (int mt=0;mt<4;mt++){
            uint32_t o = (uint32_t)((wm*64 + mt*16 + g)*48 + tig*4);
            ah[mt][0] = lds32(sA + o);
            ah[mt][1] = lds32(sA + o + 8*48);
            ah[mt][2] = lds32(sA + o + 16);
            ah[mt][3] = lds32(sA + o + 8*48 + 16);
            al[mt][0] = lds32(sAl + o);
            al[mt][1] = lds32(sAl + o + 8*48);
            al[mt][2] = lds32(sAl + o + 16);
            al[mt][3] = lds32(sAl + o + 8*48 + 16);
        }
        // B frags (B^T stored [n][k]): b0=(k=2t,n=g) b1=(k=2t+8,n=g)
        #pragma unroll
        for (int nt=0;nt<8;nt++){
            uint32_t o = (uint32_t)((wn*64 + nt*8 + g)*48 + tig*4);
            uint32_t b[2];
            b[0] = lds32(sB + o);
            b[1] = lds32(sB + o + 16);
            #pragma unroll
            for (int mt=0;mt<4;mt++){
                mma16816h(acc[mt][nt], ah[mt], b);
                mma16816h(acc[mt][nt], al[mt], b);
            }
        }
        __syncthreads();
        if (c+2 < chunks) ISSUE(c & 1, (c+2)*BK);
    }
    #undef ISSUE

    // epilogue: c0,c1 -> (g, 2t..2t+1); c2,c3 -> (g+8, 2t..2t+1)
    int t2 = tig*2;
    #pragma unroll
    for (int mt=0;mt<4;mt++){
        int m = m0 + wm*64 + mt*16 + g;
        #pragma unroll
        for (int nt=0;nt<8;nt++){
            int n = n0 + wn*64 + nt*8 + t2;
            float b0v = bias ? bias[n]   : 0.f;
            float b1v = bias ? bias[n+1] : 0.f;
            float2 r0; r0.x = acc[mt][nt][0] + b0v; r0.y = acc[mt][nt][1] + b1v;
            float2 r1; r1.x = acc[mt][nt][2] + b0v; r1.y = acc[mt][nt][3] + b1v;
            *(float2*)(C + (size_t)m*ldc + n)     = r0;
            *(float2*)(C + (size_t)(m+8)*ldc + n) = r1;
        }
    }
}

__global__ void __launch_bounds__(128,2) gemm_proj_kernel(const float* __restrict__ bq){
    int combo = blockIdx.z;
    const __half *Ah,*Al,*Bw; const float* bias; float* C;
    switch (combo){
    case 0: Ah=g_no_hi;  Al=g_no_lo;  Bw=g_Wqt; bias=bq;      C=g_wq_new; break;
    case 1: Ah=g_cur_hi; Al=g_cur_lo; Bw=g_Wqt; bias=bq;      C=g_wq_cur; break;
    case 2: Ah=g_no_hi;  Al=g_no_lo;  Bw=g_Wct; bias=nullptr; C=g_uh_new; break;
    default:Ah=g_cur_hi; Al=g_cur_lo; Bw=g_Wct; bias=nullptr; C=g_uh_cur; break;
    }
    gemm_body(Ah, Al, Bw, ND, bias, C, ND);
}

__global__ void __launch_bounds__(128,2) gemm_out_kernel(const float* __restrict__ bout, float* __restrict__ out){
    gemm_body(g_amix_hi, g_amix_lo, g_Wot, 2*ND, bout, out, ND);
}

// ================= fused attention: 2 t-rows per warp (R10-proven, unchanged) =================
__global__ void __launch_bounds__(256) attn_kernel(
    const float* __restrict__ cur, const float* __restrict__ no,
    const float* __restrict__ v)
{
    __shared__ float sc[16][128];
    __shared__ float pm[128][16];

    int dir = blockIdx.z;
    int bb  = blockIdx.y;
    int t0  = blockIdx.x * 16;
    const float* wq  = dir ? g_wq_cur : g_wq_new;
    const float* uh  = dir ? g_uh_new : g_uh_cur;
    const float* mem = dir ? no       : cur;
    float*       cO  = dir ? g_c2     : g_c1;

    int tid = threadIdx.x, w = tid >> 5, lane = tid & 31;

    float4 v4[4], qa[4], qb[4];
    {
        const float* ra = wq + (size_t)(bb*NL + t0 + w)*ND;
        const float* rb = wq + (size_t)(bb*NL + t0 + w + 8)*ND;
        #pragma unroll
        for (int i=0;i<4;i++){
            v4[i] = *(const float4*)(v  + lane*4 + 128*i);
            qa[i] = *(const float4*)(ra + lane*4 + 128*i);
            qb[i] = *(const float4*)(rb + lane*4 + 128*i);
        }
    }
    for (int s=0; s<NL; s++){
        const float* urow = uh + (size_t)(bb*NL + s)*ND;
        float acca = 0.f, accb = 0.f;
        #pragma unroll
        for (int i=0;i<4;i++){
            float4 u = *(const float4*)(urow + lane*4 + 128*i);
            acca += v4[i].x * tanh_apx(qa[i].x + u.x);
            accb += v4[i].x * tanh_apx(qb[i].x + u.x);
            acca += v4[i].y * tanh_apx(qa[i].y + u.y);
            accb += v4[i].y * tanh_apx(qb[i].y + u.y);
            acca += v4[i].z * tanh_apx(qa[i].z + u.z);
            accb += v4[i].z * tanh_apx(qb[i].z + u.z);
            acca += v4[i].w * tanh_apx(qa[i].w + u.w);
            accb += v4[i].w * tanh_apx(qb[i].w + u.w);
        }
        #pragma unroll
        for (int off=16; off; off>>=1){
            acca += __shfl_xor_sync(0xffffffffu, acca, off);
            accb += __shfl_xor_sync(0xffffffffu, accb, off);
        }
        if (lane == 0){ sc[w][s] = acca; sc[w+8][s] = accb; }
    }
    __syncwarp();

    #pragma unroll
    for (int rr=0; rr<2; rr++){
        int r = w + rr*8;
        float sv[4];
        #pragma unroll
        for (int i=0;i<4;i++) sv[i] = sc[r][lane + 32*i];
        float mx = fmaxf(fmaxf(sv[0],sv[1]), fmaxf(sv[2],sv[3]));
        #pragma unroll
        for (int off=16; off; off>>=1)
            mx = fmaxf(mx, __shfl_xor_sync(0xffffffffu, mx, off));
        float e[4], sum = 0.f;
        #pragma unroll
        for (int i=0;i<4;i++){ e[i] = __expf(sv[i]-mx); sum += e[i]; }
        #pragma unroll
        for (int off=16; off; off>>=1)
            sum += __shfl_xor_sync(0xffffffffu, sum, off);
        float inv = 1.f / sum;
        #pragma unroll
        for (int i=0;i<4;i++) pm[lane + 32*i][r] = e[i]*inv;
    }
    __syncthreads();

    int d0 = tid, d1 = tid + 256;
    float a0[16], a1[16];
    #pragma unroll
    for (int t=0;t<16;t++){ a0[t]=0.f; a1[t]=0.f; }
    for (int s=0; s<NL; s++){
        const float* mrow = mem + (size_t)(bb*NL + s)*ND;
        float m0v = __ldg(mrow + d0);
        float m1v = __ldg(mrow + d1);
        #pragma unroll
        for (int q4i=0;q4i<4;q4i++){
            float4 p = *(const float4*)&pm[s][q4i*4];
            a0[q4i*4+0]+=p.x*m0v; a1[q4i*4+0]+=p.x*m1v;
            a0[q4i*4+1]+=p.y*m0v; a1[q4i*4+1]+=p.y*m1v;
            a0[q4i*4+2]+=p.z*m0v; a1[q4i*4+2]+=p.z*m1v;
            a0[q4i*4+3]+=p.w*m0v; a1[q4i*4+3]+=p.w*m1v;
        }
    }
    #pragma unroll
    for (int t=0;t<16;t++){
        float* crow = cO + (size_t)(bb*NL + t0 + t)*ND;
        crow[d0] = a0[t];
        crow[d1] = a1[t];
    }
}

// ================= launch =================
extern "C" void kernel_launch(void* const* d_in, const int* in_sizes, int n_in,
                              void* d_out, int out_size)
{
    const float* cur  = (const float*)d_in[0];
    const float* no   = (const float*)d_in[1];
    const float* Wq   = (const float*)d_in[2];
    const float* bq   = (const float*)d_in[3];
    const float* Wc   = (const float*)d_in[4];
    const float* v    = (const float*)d_in[5];
    const float* Wout = (const float*)d_in[6];
    const float* bout = (const float*)d_in[7];
    const float* mix  = (const float*)d_in[8];
    float* out = (float*)d_out;

    split_kernel<<<2048, 256>>>(no,  0);
    split_kernel<<<2048, 256>>>(cur, 1);
    splitT_kernel<<<dim3(ND/32, ND/32),   dim3(32,8)>>>(Wq,   0, ND,   ND);
    splitT_kernel<<<dim3(ND/32, ND/32),   dim3(32,8)>>>(Wc,   1, ND,   ND);
    splitT_kernel<<<dim3(ND/32, 2*ND/32), dim3(32,8)>>>(Wout, 2, 2*ND, ND);

    gemm_proj_kernel<<<dim3(NROWS/128, ND/128, 4), 128, GSMEM>>>(bq);

    attn_kernel<<<dim3(NL/16, NB, 2), 256>>>(cur, no, v);

    mix_split_kernel<<<NROWS*2*ND/(4*256), 256>>>(no, cur, mix);
    gemm_out_kernel<<<dim3(NROWS/128, ND/128), 128, GSMEM>>>(bout, out);
}